// round 2
// baseline (speedup 1.0000x reference)
#include <cuda_runtime.h>
#include <cstdint>

// Problem constants
#define B_ROWS    1024
#define IN_FEAT   76800
#define IN_G      19200     // IN_FEAT/4 (float4 / int8x4 groups)
#define OUT_FEAT  10
#define W_ELEMS   (OUT_FEAT * IN_FEAT)   // 768000
#define W_G       (OUT_FEAT * IN_G)      // 192000 packed groups

// Fused kernel tiling: 148 CTAs = 4 slices x 37 row-groups (one wave, co-resident)
#define NSLICE    4
#define QUADS     37
#define SLICE_G   (IN_G / NSLICE)        // 4800 groups per slice
#define T_MAIN    320
#define K_TOT     (SLICE_G / T_MAIN)     // 15 k-steps per thread
#define K_REG     7                      // k-steps with weights in registers
#define K_SMEM    (K_TOT - K_REG)        // 8 k-steps with weights in smem
#define NWARP     (T_MAIN / 32)          // 10

// wsum reduction
#define WSUM_BLOCKS 125
#define WSUM_THREADS 256

// ---------------- device scratch (static, allocation-free) ----------------
__device__ float    g_wpart[WSUM_BLOCKS];
__device__ float    g_wscale;               // 1/clip(mean|W|,eps)
__device__ float    g_winv;                 // clip(mean|W|,eps)
__device__ float    g_rowscale[B_ROWS];     // 127/clip(rowmax,eps)
__device__ unsigned g_tw[W_G];              // ternary weights, packed int8x4, layout [o][g]
__device__ int      g_dot[B_ROWS * NSLICE * OUT_FEAT];
__device__ unsigned g_pmax[B_ROWS * NSLICE];  // per (row,slice) absmax bits | 1 (flag)

// ---------------- kernel 0: zero the flag array (every launch/replay) ----------------
__global__ void k_init(void) {
    g_pmax[blockIdx.x * 1024 + threadIdx.x] = 0u;   // grid 4 x 1024 = 4096
}

// ---------------- kernel 1: sum |W| ----------------
__global__ void k_wsum(const float4* __restrict__ w4) {
    float s = 0.f;
    int idx = blockIdx.x * WSUM_THREADS + threadIdx.x;
    #pragma unroll
    for (int k = 0; k < 6; k++) {   // 125*256*6 = 192000 exactly
        float4 v = w4[idx + k * WSUM_BLOCKS * WSUM_THREADS];
        s += fabsf(v.x) + fabsf(v.y) + fabsf(v.z) + fabsf(v.w);
    }
    #pragma unroll
    for (int d = 16; d; d >>= 1) s += __shfl_down_sync(0xffffffffu, s, d);
    __shared__ float red[8];
    int warp = threadIdx.x >> 5, lane = threadIdx.x & 31;
    if (lane == 0) red[warp] = s;
    __syncthreads();
    if (threadIdx.x < 8) {
        float v = red[threadIdx.x];
        #pragma unroll
        for (int d = 4; d; d >>= 1) v += __shfl_down_sync(0xffu, v, d);
        if (threadIdx.x == 0) g_wpart[blockIdx.x] = v;
    }
}

// ---------------- kernel 2: finalize wscale ----------------
__global__ void k_wscale(void) {
    float s = (threadIdx.x < WSUM_BLOCKS) ? g_wpart[threadIdx.x] : 0.f;
    #pragma unroll
    for (int d = 16; d; d >>= 1) s += __shfl_down_sync(0xffffffffu, s, d);
    __shared__ float red[4];
    int warp = threadIdx.x >> 5, lane = threadIdx.x & 31;
    if (lane == 0) red[warp] = s;
    __syncthreads();
    if (threadIdx.x == 0) {
        float total = red[0] + red[1] + red[2] + red[3];
        float mean = fmaxf(total / (float)W_ELEMS, 1e-5f);
        g_winv = mean;
        g_wscale = 1.f / mean;
    }
}

// ---------------- kernel 3: ternarize W into packed int8x4 ----------------
__global__ void k_ternary(const float4* __restrict__ w4) {
    int i = blockIdx.x * 256 + threadIdx.x;   // grid 750*256 = 192000
    float ws = g_wscale;
    float4 v = w4[i];
    int t0 = (int)fminf(1.f, fmaxf(-1.f, rintf(v.x * ws)));
    int t1 = (int)fminf(1.f, fmaxf(-1.f, rintf(v.y * ws)));
    int t2 = (int)fminf(1.f, fmaxf(-1.f, rintf(v.z * ws)));
    int t3 = (int)fminf(1.f, fmaxf(-1.f, rintf(v.w * ws)));
    g_tw[i] = (unsigned)((t0 & 0xFF) | ((t1 & 0xFF) << 8) | ((t2 & 0xFF) << 16) | (t3 << 24));
}

// magic-number quantize of a float4 into a packed int8x4 word.
// Two-step FMUL+FADD matches ref's round(fl(x*s)) with round-half-even exactly.
__device__ __forceinline__ unsigned quant_pack(float4 v, float as) {
    float f0 = __fadd_rn(__fmul_rn(v.x, as), 12582912.f);   // 1.5*2^23
    float f1 = __fadd_rn(__fmul_rn(v.y, as), 12582912.f);
    float f2 = __fadd_rn(__fmul_rn(v.z, as), 12582912.f);
    float f3 = __fadd_rn(__fmul_rn(v.w, as), 12582912.f);
    unsigned p01 = __byte_perm(__float_as_uint(f0), __float_as_uint(f1), 0x0040);
    unsigned p23 = __byte_perm(__float_as_uint(f2), __float_as_uint(f3), 0x0040);
    return __byte_perm(p01, p23, 0x5410);
}

// ---------------- kernel 4: fused absmax + quantize + ternary GEMV ----------------
// grid = 148 (exactly one wave, all CTAs co-resident -> spin-flags are safe).
// CTA c: slice s = c&3, row-group q = c>>2; rows r = q, q+37, ...
// Pass 1 loads the 76.8KB slice (fills L1), publishes slice absmax via volatile
// flag; spins for the 3 sibling slices; pass 2 re-reads the slice from L1.
__global__ void __launch_bounds__(T_MAIN, 1) k_main(const float4* __restrict__ x4) {
    extern __shared__ unsigned smem[];
    unsigned* sw    = smem;                                   // [10][K_SMEM*T_MAIN]
    int*      sred  = (int*)(smem + OUT_FEAT * K_SMEM * T_MAIN); // [NWARP][10]
    float*    sredf = (float*)sred;                           // alias for max stage
    float*    sb    = (float*)(sred + NWARP * OUT_FEAT);      // broadcast scale

    const int c = blockIdx.x;
    const int s = c & 3;
    const int q = c >> 2;
    const int tid = threadIdx.x;
    const int warp = tid >> 5, lane = tid & 31;
    const int gbase = s * SLICE_G;

    // --- weights: 7 k-steps into registers, 8 k-steps into smem (one-time) ---
    unsigned wreg[K_REG][OUT_FEAT];
    #pragma unroll
    for (int k = 0; k < K_REG; k++)
        #pragma unroll
        for (int o = 0; o < OUT_FEAT; o++)
            wreg[k][o] = g_tw[o * IN_G + gbase + tid + k * T_MAIN];
    #pragma unroll
    for (int o = 0; o < OUT_FEAT; o++)
        #pragma unroll
        for (int kk = 0; kk < K_SMEM; kk++)
            sw[(o * K_SMEM + kk) * T_MAIN + tid] =
                g_tw[o * IN_G + gbase + tid + (K_REG + kk) * T_MAIN];
    __syncthreads();

    for (int row = q; row < B_ROWS; row += QUADS) {
        const float4* xr = x4 + (size_t)row * IN_G + gbase;

        // ---- pass 1: slice absmax (loads cache in L1) ----
        float m = 0.f;
        #pragma unroll
        for (int k = 0; k < K_TOT; k++) {
            float4 v = xr[tid + k * T_MAIN];
            m = fmaxf(m, fmaxf(fmaxf(fabsf(v.x), fabsf(v.y)),
                               fmaxf(fabsf(v.z), fabsf(v.w))));
        }
        #pragma unroll
        for (int d = 16; d; d >>= 1) m = fmaxf(m, __shfl_down_sync(0xffffffffu, m, d));
        if (lane == 0) sredf[warp] = m;
        __syncthreads();

        // ---- publish + spin for sibling slices (no atomics, no fences) ----
        if (tid == 0) {
            float bm = sredf[0];
            #pragma unroll
            for (int w = 1; w < NWARP; w++) bm = fmaxf(bm, sredf[w]);
            volatile unsigned* slot = g_pmax + row * NSLICE;
            slot[s] = __float_as_uint(bm) | 1u;     // nonzero marker, <=1 ulp perturbation
            unsigned a0, a1, a2, a3;
            do {
                a0 = slot[0]; a1 = slot[1]; a2 = slot[2]; a3 = slot[3];
                if (a0 && a1 && a2 && a3) break;
                __nanosleep(60);
            } while (true);
            float rm = fmaxf(fmaxf(__uint_as_float(a0), __uint_as_float(a1)),
                             fmaxf(__uint_as_float(a2), __uint_as_float(a3)));
            float asc = 127.f / fmaxf(rm, 1e-5f);
            sb[0] = asc;
            if (s == 0) g_rowscale[row] = asc;
        }
        __syncthreads();
        const float as = sb[0];

        // ---- pass 2: quantize (L1 hits) + dp4a vs ternary weights ----
        int acc[OUT_FEAT];
        #pragma unroll
        for (int o = 0; o < OUT_FEAT; o++) acc[o] = 0;

        #pragma unroll
        for (int k = 0; k < K_REG; k++) {
            unsigned qw = quant_pack(xr[tid + k * T_MAIN], as);
            #pragma unroll
            for (int o = 0; o < OUT_FEAT; o++)
                acc[o] = __dp4a((int)qw, (int)wreg[k][o], acc[o]);
        }
        #pragma unroll
        for (int kk = 0; kk < K_SMEM; kk++) {
            unsigned qw = quant_pack(xr[tid + (K_REG + kk) * T_MAIN], as);
            #pragma unroll
            for (int o = 0; o < OUT_FEAT; o++)
                acc[o] = __dp4a((int)qw, (int)sw[(o * K_SMEM + kk) * T_MAIN + tid], acc[o]);
        }

        // ---- reduce 320 threads -> 10 partial dots ----
        #pragma unroll
        for (int o = 0; o < OUT_FEAT; o++) {
            #pragma unroll
            for (int d = 16; d; d >>= 1)
                acc[o] += __shfl_down_sync(0xffffffffu, acc[o], d);
        }
        if (lane == 0) {
            #pragma unroll
            for (int o = 0; o < OUT_FEAT; o++) sred[warp * OUT_FEAT + o] = acc[o];
        }
        __syncthreads();
        if (tid < OUT_FEAT) {
            int sum = 0;
            #pragma unroll
            for (int w = 0; w < NWARP; w++) sum += sred[w * OUT_FEAT + tid];
            g_dot[(row * NSLICE + s) * OUT_FEAT + tid] = sum;
        }
        __syncthreads();   // protect sred/sredf reuse next row
    }
}

// ---------------- kernel 5: combine slices, scale, bias, softmax ----------------
__global__ void k_finish(const float* __restrict__ bias, float* __restrict__ out) {
    int row = blockIdx.x * 128 + threadIdx.x;   // grid 8 x 128 = 1024
    float inv_as = 1.f / g_rowscale[row];
    float coef = inv_as * g_winv;
    const int* dp = g_dot + row * NSLICE * OUT_FEAT;
    float logit[OUT_FEAT];
    float m = -3.4e38f;
    #pragma unroll
    for (int o = 0; o < OUT_FEAT; o++) {
        int d = dp[0 * OUT_FEAT + o] + dp[1 * OUT_FEAT + o]
              + dp[2 * OUT_FEAT + o] + dp[3 * OUT_FEAT + o];
        logit[o] = coef * (float)d + bias[o];
        m = fmaxf(m, logit[o]);
    }
    float ssum = 0.f;
    #pragma unroll
    for (int o = 0; o < OUT_FEAT; o++) { logit[o] = expf(logit[o] - m); ssum += logit[o]; }
    float inv_s = 1.f / ssum;
    #pragma unroll
    for (int o = 0; o < OUT_FEAT; o++) out[row * OUT_FEAT + o] = logit[o] * inv_s;
}

// ---------------- launch ----------------
extern "C" void kernel_launch(void* const* d_in, const int* in_sizes, int n_in,
                              void* d_out, int out_size) {
    const float4* x4 = (const float4*)d_in[0];   // [1024,3,160,160] fp32
    const float4* w4 = (const float4*)d_in[1];   // [10,76800] fp32
    const float*  b  = (const float*)d_in[2];    // [10]
    float* out = (float*)d_out;

    static int smem_set = 0;
    const int main_smem = OUT_FEAT * K_SMEM * T_MAIN * 4        // weights: 102400
                        + NWARP * OUT_FEAT * 4 + 16;            // sred + broadcast
    if (!smem_set) {
        cudaFuncSetAttribute(k_main, cudaFuncAttributeMaxDynamicSharedMemorySize, main_smem);
        smem_set = 1;
    }

    k_init<<<4, 1024>>>();
    k_wsum<<<WSUM_BLOCKS, WSUM_THREADS>>>(w4);
    k_wscale<<<1, 128>>>();
    k_ternary<<<W_G / 256, 256>>>(w4);
    k_main<<<NSLICE * QUADS, T_MAIN, main_smem>>>(x4);
    k_finish<<<B_ROWS / 128, 128>>>(b, out);
}